// round 5
// baseline (speedup 1.0000x reference)
#include <cuda_runtime.h>

#define F_FIELDS 17
#define HH 300
#define WW 400
#define H_F 38
#define W_F 50
#define NPTS (F_FIELDS * H_F * W_F)       // 32300
#define TILE 64
#define TRR 5                              // ceil(300/64)
#define TCC 7                              // ceil(400/64)
#define NTILES (F_FIELDS * TRR * TCC)      // 595
#define CAP 1024

// Scratch (static __device__ globals: allowed; zero-initialized at load).
// g_counts invariant: zero at entry of phase1 on every execution — phase2
// re-zeroes it, so graph replays stay deterministic.
__device__ int    g_counts[NTILES];
__device__ int    g_list[NTILES * CAP];
__device__ float4 g_pa[NPTS];              // px, py, value, ninv
__device__ float4 g_pb[NPTS];              // trunc2, pack(y0,y1), pack(x0,x1), -

__global__ void __launch_bounds__(256) cifhr_bin(const float* __restrict__ x) {
    const int p = blockIdx.x * blockDim.x + threadIdx.x;
    if (p >= NPTS) return;
    const int f = p / (H_F * W_F);
    const int hw = p - f * (H_F * W_F);
    const float* base = x + (size_t)f * 5 * (H_F * W_F) + hw;

    const float v = base[0];
    if (!(v >= 0.1f)) return;                       // v >= V_TH
    const float scale = base[4 * H_F * W_F];
    if (!(scale * 8.0f >= 0.0f)) return;            // MIN_SCALE = 0

    const float px = base[1 * H_F * W_F] * 8.0f;
    const float py = base[2 * H_F * W_F] * 8.0f;
    const float sigma  = fmaxf(1.0f, 4.0f * scale);
    const float sigma2 = sigma * sigma;
    const float tr2    = 4.0f * sigma2;
    const float ninv   = -0.5f / sigma2;
    const float value  = v * 0.0625f;               // v/16

    const int cx = (int)rintf(px);                  // round-half-even == jnp.round
    const int cy = (int)rintf(py);
    int rb = (int)floorf(2.0f * sigma + 0.5f);      // |d|>rb => d2>trunc2 (exact)
    if (rb > 13) rb = 13;                           // reference window cap

    const int y0 = max(cy - rb, 0), y1 = min(cy + rb, HH - 1);
    const int x0 = max(cx - rb, 0), x1 = min(cx + rb, WW - 1);
    if (y0 > y1 || x0 > x1) return;

    g_pa[p] = make_float4(px, py, value, ninv);
    g_pb[p] = make_float4(tr2, __int_as_float(y0 | (y1 << 16)),
                          __int_as_float(x0 | (x1 << 16)), 0.0f);

    const int ty0 = y0 >> 6, ty1 = y1 >> 6;         // <= 4
    const int tx0 = x0 >> 6, tx1 = x1 >> 6;         // <= 6
    for (int ty = ty0; ty <= ty1; ty++)
        for (int tx = tx0; tx <= tx1; tx++) {
            const int t = (f * TRR + ty) * TCC + tx;
            const int idx = atomicAdd(&g_counts[t], 1);
            if (idx < CAP) g_list[t * CAP + idx] = p;
        }
}

// One block per 64x64 output tile. Warps splat candidates into a shared tile;
// final write is a plain store fused with cifhr-add and clamp.
__global__ void __launch_bounds__(256) cifhr_tile(
    const float* __restrict__ cifhr, float* __restrict__ out
) {
    __shared__ float s_acc[TILE * TILE];            // 16 KB
    const int t = blockIdx.x;
    const int f = t / (TRR * TCC);
    const int rem = t - f * (TRR * TCC);
    const int tyb = (rem / TCC) * TILE;
    const int txb = (rem % TCC) * TILE;
    const int tid = threadIdx.x;
    const int wid = tid >> 5, lane = tid & 31;

    #pragma unroll
    for (int i = tid; i < TILE * TILE; i += 256) s_acc[i] = 0.0f;
    __syncthreads();

    const int n = min(g_counts[t], CAP);

    for (int i = wid; i < n; i += 8) {
        const int p = g_list[t * CAP + i];
        const float4 a = g_pa[p];                   // px,py,val,ninv (broadcast LDG)
        const float4 b = g_pb[p];
        const int ybb = __float_as_int(b.y);
        const int xbb = __float_as_int(b.z);
        const int ry0 = max(ybb & 0xffff, tyb);
        const int ry1 = min(ybb >> 16, tyb + TILE - 1);
        const int rx0 = max(xbb & 0xffff, txb);
        const int rx1 = min(xbb >> 16, txb + TILE - 1);
        const int w = rx1 - rx0 + 1;
        const int h = ry1 - ry0 + 1;
        if (w <= 0 || h <= 0) continue;             // defensive; binning makes nonempty
        const int ncell = w * h;
        const float k8 = a.w * 0.125f;              // ninv/8

        int row = lane / w;
        int col = lane - row * w;
        const int drow = 32 / w;
        const int dcol = 32 - drow * w;
        for (int c = lane; c < ncell; c += 32, row += drow, col += dcol) {
            if (col >= w) { col -= w; row += 1; }
            const int yy = ry0 + row;
            const int xx = rx0 + col;
            const float dy = (float)yy - a.y;
            const float dx = (float)xx - a.x;
            const float dy2 = dy * dy, dx2 = dx * dx;
            const float d2 = dy2 + dx2;
            if (d2 <= b.x) {
                float g = fmaf(d2, k8, 1.0f);       // (1 + t/8)^8, t = -d2/(2*s2)
                g = g * g; g = g * g; g = g * g;
                if (dy2 < 0.25f && dx2 < 0.25f) g = 1.0f;   // nearest override
                atomicAdd(&s_acc[(yy - tyb) * TILE + (xx - txb)], a.z * g);
            }
        }
    }
    __syncthreads();
    if (tid == 0) g_counts[t] = 0;                  // reset for next replay

    // Writeout: 16 px/thread as 4x float4, fused cifhr-add + clamp.
    const int lx  = (tid & 15) << 2;                // 0..60
    const int ly0 = tid >> 4;                       // 0..15
    const int gx = txb + lx;
    if (gx < WW) {                                  // WW%4==0 -> whole float4 in
        #pragma unroll
        for (int r = 0; r < 4; r++) {
            const int ly = ly0 + r * 16;
            const int gy = tyb + ly;
            if (gy < HH) {
                const int idx = (f * HH + gy) * WW + gx;
                const float4 cv = *reinterpret_cast<const float4*>(cifhr + idx);
                const float* s = &s_acc[ly * TILE + lx];
                float4 o;
                o.x = fminf(cv.x + s[0], 1.0f);
                o.y = fminf(cv.y + s[1], 1.0f);
                o.z = fminf(cv.z + s[2], 1.0f);
                o.w = fminf(cv.w + s[3], 1.0f);
                *reinterpret_cast<float4*>(out + idx) = o;
            }
        }
    }
}

extern "C" void kernel_launch(void* const* d_in, const int* in_sizes, int n_in,
                              void* d_out, int out_size) {
    const float* cifhr = (const float*)d_in[0];
    const float* x     = (const float*)d_in[1];
    float* out = (float*)d_out;

    cifhr_bin<<<(NPTS + 255) / 256, 256>>>(x);
    cifhr_tile<<<NTILES, 256>>>(cifhr, out);
}

// round 7
// speedup vs baseline: 1.6222x; 1.6222x over previous
#include <cuda_runtime.h>

#define F_FIELDS 17
#define HH 300
#define WW 400
#define H_F 38
#define W_F 50
#define NPTS (F_FIELDS * H_F * W_F)          // 32300
#define OUT_ELEMS (F_FIELDS * HH * WW)       // 2,040,000

// Static scratch accumulator. Zero-initialized at module load; the epilogue
// kernel re-zeroes it every run, so the "zero at entry" invariant holds for
// the correctness run and for every graph replay.
__device__ float g_scratch[OUT_ELEMS];

// One warp per point: splat the truncated-Gaussian disc into g_scratch with
// aligned red.global.add.v4.f32 (no return value -> REDG.128).
__global__ void __launch_bounds__(256) cifhr_scatter_v4(
    const float* __restrict__ x    // (17, 5, 38, 50)
) {
    const int warp = threadIdx.x >> 5;
    const int lane = threadIdx.x & 31;
    const int p = blockIdx.x * 8 + warp;
    if (p >= NPTS) return;

    const int f = p / (H_F * W_F);
    const int hw = p - f * (H_F * W_F);
    const float* base = x + (size_t)f * 5 * (H_F * W_F) + hw;

    const float v = base[0];
    if (!(v >= 0.1f)) return;                       // v >= V_TH
    const float scale = base[4 * H_F * W_F];
    if (!(scale * 8.0f >= 0.0f)) return;            // MIN_SCALE = 0

    const float px = base[1 * H_F * W_F] * 8.0f;
    const float py = base[2 * H_F * W_F] * 8.0f;

    const float sigma  = fmaxf(1.0f, 4.0f * scale); // max(1, 0.5*scale*8)
    const float sigma2 = sigma * sigma;
    const float trunc2 = 4.0f * sigma2;
    const float k8     = (-0.5f / sigma2) * 0.125f; // ninv/8
    const float value  = v * 0.0625f;               // v/16

    const int cx = (int)rintf(px);                  // round-half-even == jnp.round
    const int cy = (int)rintf(py);

    // |dy| > 2*sigma + 0.5  =>  (yy-py)^2 > 4*sigma^2 : provably fails mask
    int rb = (int)floorf(2.0f * sigma + 0.5f);
    if (rb > 13) rb = 13;

    const int y0 = max(cy - rb, 0), y1 = min(cy + rb, HH - 1);
    const int x0 = max(cx - rb, 0), x1 = min(cx + rb, WW - 1);
    if (y0 > y1 || x0 > x1) return;

    const int xs = x0 & ~3;                         // aligned start, >= 0
    const int Wg = (((x1 | 3) + 1) - xs) >> 2;      // groups/row; end <= 400
    const int nrows = y1 - y0 + 1;
    const int Ng = nrows * Wg;

    int row = lane / Wg;
    int gx  = lane - row * Wg;
    const int drow = 32 / Wg;
    const int dgx  = 32 - drow * Wg;

    float* __restrict__ fout = g_scratch + (size_t)f * HH * WW;

    for (int g = lane; g < Ng; g += 32, row += drow, gx += dgx) {
        if (gx >= Wg) { gx -= Wg; row += 1; }
        const int yy = y0 + row;
        const int xb = xs + (gx << 2);

        const float fdy = (float)yy - py;
        const float dy2 = fdy * fdy;
        // whole 4-group outside disc row-extent? (cheap reject before 4x math)
        const float rem = trunc2 - dy2;
        if (rem < 0.0f) continue;
        const bool ny = dy2 < 0.25f;

        float c[4];
        bool any = false;
        #pragma unroll
        for (int j = 0; j < 4; j++) {
            const int xx = xb + j;
            const float fdx = (float)xx - px;
            const float dx2 = fdx * fdx;
            const float d2 = dy2 + dx2;
            float t = fmaf(d2, k8, 1.0f);           // (1 + t/8)^8
            t = t * t; t = t * t; t = t * t;
            const float gg = (ny && dx2 < 0.25f) ? 1.0f : t;
            const bool in = (xx >= x0) & (xx <= x1) & (dx2 <= rem);
            c[j] = in ? value * gg : 0.0f;
            any |= in;
        }

        if (any) {
            float* addr = fout + yy * WW + xb;      // 16B aligned, in-row
            asm volatile("red.global.add.v4.f32 [%0], {%1,%2,%3,%4};"
                         :: "l"(addr), "f"(c[0]), "f"(c[1]), "f"(c[2]), "f"(c[3])
                         : "memory");
        }
    }
}

// Fused epilogue: out = min(cifhr + scratch, 1)  AND  scratch <- 0.
// ILP-4 float4 grid-stride to hide latency.
__global__ void __launch_bounds__(256) cifhr_finish(
    const float4* __restrict__ cifhr, float4* __restrict__ out
) {
    float4* __restrict__ sc = reinterpret_cast<float4*>(g_scratch);
    const int n4 = OUT_ELEMS / 4;                   // 510000
    const int stride = gridDim.x * blockDim.x;
    int i = blockIdx.x * blockDim.x + threadIdx.x;

    for (; i + 3 * stride < n4; i += 4 * stride) {
        float4 s0 = sc[i], s1 = sc[i + stride], s2 = sc[i + 2 * stride], s3 = sc[i + 3 * stride];
        float4 c0 = cifhr[i], c1 = cifhr[i + stride], c2 = cifhr[i + 2 * stride], c3 = cifhr[i + 3 * stride];
        float4 z = make_float4(0.f, 0.f, 0.f, 0.f);
        float4 o0, o1, o2, o3;
        o0.x = fminf(c0.x + s0.x, 1.f); o0.y = fminf(c0.y + s0.y, 1.f);
        o0.z = fminf(c0.z + s0.z, 1.f); o0.w = fminf(c0.w + s0.w, 1.f);
        o1.x = fminf(c1.x + s1.x, 1.f); o1.y = fminf(c1.y + s1.y, 1.f);
        o1.z = fminf(c1.z + s1.z, 1.f); o1.w = fminf(c1.w + s1.w, 1.f);
        o2.x = fminf(c2.x + s2.x, 1.f); o2.y = fminf(c2.y + s2.y, 1.f);
        o2.z = fminf(c2.z + s2.z, 1.f); o2.w = fminf(c2.w + s2.w, 1.f);
        o3.x = fminf(c3.x + s3.x, 1.f); o3.y = fminf(c3.y + s3.y, 1.f);
        o3.z = fminf(c3.z + s3.z, 1.f); o3.w = fminf(c3.w + s3.w, 1.f);
        out[i] = o0; out[i + stride] = o1; out[i + 2 * stride] = o2; out[i + 3 * stride] = o3;
        sc[i] = z; sc[i + stride] = z; sc[i + 2 * stride] = z; sc[i + 3 * stride] = z;
    }
    for (; i < n4; i += stride) {
        float4 s = sc[i], c = cifhr[i], o;
        o.x = fminf(c.x + s.x, 1.f); o.y = fminf(c.y + s.y, 1.f);
        o.z = fminf(c.z + s.z, 1.f); o.w = fminf(c.w + s.w, 1.f);
        out[i] = o;
        sc[i] = make_float4(0.f, 0.f, 0.f, 0.f);
    }
}

extern "C" void kernel_launch(void* const* d_in, const int* in_sizes, int n_in,
                              void* d_out, int out_size) {
    const float* cifhr = (const float*)d_in[0];
    const float* x     = (const float*)d_in[1];
    float* out = (float*)d_out;

    const int warps_per_block = 8;
    const int blocks = (NPTS + warps_per_block - 1) / warps_per_block;
    cifhr_scatter_v4<<<blocks, 256>>>(x);

    // 512 blocks x 256 thr x 4 float4 ~ covers 510K float4s in one ILP-4 pass
    cifhr_finish<<<512, 256>>>((const float4*)cifhr, (float4*)out);
}